// round 10
// baseline (speedup 1.0000x reference)
#include <cuda_runtime.h>
#include <cuda_fp16.h>

#define NN   100000
#define EE   1600000
#define CIN  1024
#define HD   64
#define ZDIM 32

#define NBLK ((NN + 255) / 256)   // 391

// ---------------- scratch (static __device__ — no allocation) ----------------
__device__ int   g_is64;
__device__ int   g_total;
__device__ int   g_deg[NN];
__device__ int   g_off[NN];
__device__ int   g_cur[NN];
__device__ int   g_csr[EE];
__device__ float g_dinv[NN];
__device__ unsigned g_t1h[NN * 32];   // x @ Wg1, fp16 half2 words (12.8 MB)
__device__ unsigned g_t2h[NN * 16];   // encoder z, fp16 half2 words (6.4 MB)
__device__ unsigned g_dzp[NN * 32];   // decoder hidden, fp16 half2 frag words (12.8 MB)

// fp16 frag-packed weights
__device__ __align__(16) unsigned g_Wg1p[64 * 8 * 64];     // 128 KB
__device__ __align__(16) unsigned g_Wf2p[4 * 128 * 64];    // 128 KB

// ---------------- helpers ----------------
__device__ __forceinline__ unsigned h2pack(float x0, float x1) {
    __half2 h = __float22half2_rn(make_float2(x0, x1));
    return *reinterpret_cast<unsigned*>(&h);
}
__device__ __forceinline__ float2 h2unpack(unsigned w) {
    return __half22float2(*reinterpret_cast<__half2*>(&w));
}

__device__ __forceinline__ void mma16816h(float* c, const unsigned* a, unsigned b0, unsigned b1) {
    asm volatile(
        "mma.sync.aligned.m16n8k16.row.col.f32.f16.f16.f32 "
        "{%0,%1,%2,%3}, {%4,%5,%6,%7}, {%8,%9}, {%0,%1,%2,%3};\n"
        : "+f"(c[0]), "+f"(c[1]), "+f"(c[2]), "+f"(c[3])
        : "r"(a[0]), "r"(a[1]), "r"(a[2]), "r"(a[3]), "r"(b0), "r"(b1));
}

__device__ __forceinline__ void cp16(unsigned smem_addr, const void* gptr) {
    asm volatile("cp.async.ca.shared.global [%0], [%1], 16;\n"
                 :: "r"(smem_addr), "l"(gptr));
}
__device__ __forceinline__ void cp_commit() { asm volatile("cp.async.commit_group;\n"); }
__device__ __forceinline__ void cp_wait1()  { asm volatile("cp.async.wait_group 1;\n" ::: "memory"); }

// ---------------- init: detect edge dtype + zero degrees + reset cursor ----------------
__global__ void init_kernel(const int* __restrict__ ei32) {
    int i = blockIdx.x * blockDim.x + threadIdx.x;
    if (i < NN) g_deg[i] = 0;
    if (blockIdx.x == 0 && threadIdx.x == 0) {
        int nz = 0;
        for (int k = 0; k < 64; k++) nz |= (ei32[2 * k + 1] != 0);
        g_is64 = nz ? 0 : 1;
        g_total = 0;
    }
}

__global__ void hist_kernel(const void* __restrict__ ei) {
    int is64 = g_is64;
    int e = blockIdx.x * blockDim.x + threadIdx.x;
    if (e < EE) {
        int d = is64 ? (int)((const long long*)ei)[EE + e]
                     : ((const int*)ei)[EE + e];
        atomicAdd(&g_deg[d], 1);
    }
}

// ---- alloc: warp-aggregated offset assignment (replaces the 3-kernel scan) ----
__global__ void alloc_kernel() {
    int i = blockIdx.x * blockDim.x + threadIdx.x;
    int lane = threadIdx.x & 31;
    int d = (i < NN) ? g_deg[i] : 0;
    // warp-inclusive scan of d
    int p = d;
#pragma unroll
    for (int o = 1; o < 32; o <<= 1) {
        int t = __shfl_up_sync(0xffffffffu, p, o);
        if (lane >= o) p += t;
    }
    int tot = __shfl_sync(0xffffffffu, p, 31);
    int base = 0;
    if (lane == 31) base = atomicAdd(&g_total, tot);
    base = __shfl_sync(0xffffffffu, base, 31);
    if (i < NN) {
        int off = base + p - d;
        g_off[i] = off;
        g_cur[i] = off;
        g_dinv[i] = rsqrtf((float)(d + 1));
    }
}

__global__ void scatter_kernel(const void* __restrict__ ei) {
    int is64 = g_is64;
    int e = blockIdx.x * blockDim.x + threadIdx.x;
    if (e < EE) {
        int s, d;
        if (is64) {
            s = (int)((const long long*)ei)[e];
            d = (int)((const long long*)ei)[EE + e];
        } else {
            s = ((const int*)ei)[e];
            d = ((const int*)ei)[EE + e];
        }
        int pos = atomicAdd(&g_cur[d], 1);
        g_csr[pos] = s;
    }
}

// ---------------- weight packing into fp16 frag layout ----------------
__global__ void pack_w16_kernel(const float* __restrict__ W, int K, int N,
                                unsigned* __restrict__ pw) {
    int idx = blockIdx.x * blockDim.x + threadIdx.x;
    int total = (K / 16) * (N / 8) * 64;
    if (idx >= total) return;
    int lane2 = idx & 63;
    int j = lane2 & 1;
    int lane = lane2 >> 1;
    int nb = (idx >> 6) % (N / 8);
    int kc = idx / (64 * (N / 8));
    int k0 = kc * 16 + (lane & 3) * 2 + j * 8;
    int n = nb * 8 + (lane >> 2);
    pw[idx] = h2pack(W[(long long)k0 * N + n], W[(long long)(k0 + 1) * N + n]);
}

// -------- GEMM1 (fp16 tensor core): t1[N,64] = x[N,1024] @ Wg1 --------
__global__ __launch_bounds__(256, 3) void gemm1_mma_kernel(const float* __restrict__ x) {
    __shared__ __align__(16) unsigned Bs[3 * 512];
    int tid = threadIdx.x;
    int wid = tid >> 5, lane = tid & 31;
    int gid = lane >> 2, tid4 = lane & 3;
    long long rowBase = (long long)blockIdx.x * 128 + wid * 16;

    long long r0 = rowBase + gid;
    long long r1 = r0 + 8;
    long long c0 = (r0 < NN) ? r0 : NN - 1;
    long long c1 = (r1 < NN) ? r1 : NN - 1;
    const float* p0 = x + c0 * CIN;
    const float* p1 = x + c1 * CIN;

    unsigned sbase = (unsigned)__cvta_generic_to_shared(Bs);
    int doCp = (tid < 128);

    if (doCp) cp16(sbase + tid * 16, g_Wg1p + tid * 4);
    cp_commit();
    if (doCp) cp16(sbase + 512 * 4 + tid * 16, g_Wg1p + 512 + tid * 4);
    cp_commit();

    float acc[8][4];
#pragma unroll
    for (int nb = 0; nb < 8; nb++)
#pragma unroll
        for (int q = 0; q < 4; q++) acc[nb][q] = 0.f;

    float2 a0, a1, a2, a3;
    {
        int col = tid4 * 2;
        a0 = *(const float2*)(p0 + col);
        a1 = *(const float2*)(p1 + col);
        a2 = *(const float2*)(p0 + col + 8);
        a3 = *(const float2*)(p1 + col + 8);
    }

    for (int kc = 0; kc < 64; kc++) {
        float2 n0, n1, n2, n3;
        if (kc < 63) {
            int col = (kc + 1) * 16 + tid4 * 2;
            n0 = *(const float2*)(p0 + col);
            n1 = *(const float2*)(p1 + col);
            n2 = *(const float2*)(p0 + col + 8);
            n3 = *(const float2*)(p1 + col + 8);
        }

        cp_wait1();
        __syncthreads();
        if (kc + 2 < 64 && doCp)
            cp16(sbase + ((kc + 2) % 3) * 512 * 4 + tid * 16, g_Wg1p + (kc + 2) * 512 + tid * 4);
        cp_commit();

        unsigned at[4];
        at[0] = h2pack(a0.x, a0.y);
        at[1] = h2pack(a1.x, a1.y);
        at[2] = h2pack(a2.x, a2.y);
        at[3] = h2pack(a3.x, a3.y);

        const unsigned* BsS = Bs + (kc % 3) * 512;
#pragma unroll
        for (int nb = 0; nb < 8; nb++) {
            uint2 b = *(const uint2*)(BsS + nb * 64 + lane * 2);
            mma16816h(acc[nb], at, b.x, b.y);
        }
        a0 = n0; a1 = n1; a2 = n2; a3 = n3;
    }

#pragma unroll
    for (int nb = 0; nb < 8; nb++) {
        int w = nb * 4 + tid4;
        if (r0 < NN) g_t1h[r0 * 32 + w] = h2pack(acc[nb][0], acc[nb][1]);
        if (r1 < NN) g_t1h[r1 * 32 + w] = h2pack(acc[nb][2], acc[nb][3]);
    }
}

// ------- gather1: aggregate(t1h); h = relu(.+bg1); t2h = h@Wg2 -------
// Explicit 8-wide load batching for MLP.
__global__ __launch_bounds__(256) void gather1_kernel(const float* __restrict__ bg1,
                                                      const float* __restrict__ Wg2) {
    __shared__ float Wg2s[HD * ZDIM];
    __shared__ float bg1s[HD];
    int tid = threadIdx.x;
    for (int i = tid; i < HD * ZDIM; i += 256) Wg2s[i] = Wg2[i];
    if (tid < HD) bg1s[tid] = bg1[tid];
    __syncthreads();

    int v = blockIdx.x * 8 + (tid >> 5);
    if (v >= NN) return;
    int lane = tid & 31;

    float a0a = 0.f, a0b = 0.f, a1a = 0.f, a1b = 0.f;
    int beg = g_off[v];
    int cnt = g_deg[v];
    for (int base = 0; base < cnt; base += 32) {
        int j = base + lane;
        int s = (j < cnt) ? g_csr[beg + j] : 0;
        float w = (j < cnt) ? g_dinv[s] : 0.f;
        int soff = s * 32;
        int rem = cnt - base;
        if (rem > 32) rem = 32;
        for (int qq = 0; qq * 8 < rem; qq++) {
            unsigned fv[8];
            float wv[8];
#pragma unroll
            for (int qi = 0; qi < 8; qi++) {
                int q = qq * 8 + qi;
                int ov = __shfl_sync(0xffffffffu, soff, q);
                wv[qi] = __shfl_sync(0xffffffffu, w, q);
                fv[qi] = g_t1h[ov + lane];
            }
#pragma unroll
            for (int qi = 0; qi < 8; qi++) {
                float2 f = h2unpack(fv[qi]);
                if (qi & 1) { a0b += wv[qi] * f.x; a1b += wv[qi] * f.y; }
                else        { a0a += wv[qi] * f.x; a1a += wv[qi] * f.y; }
            }
        }
    }
    float acc0 = a0a + a0b, acc1 = a1a + a1b;
    float di = g_dinv[v];
    float2 pv = h2unpack(g_t1h[(long long)v * 32 + lane]);
    float h0 = fmaxf(di * acc0 + di * di * pv.x + bg1s[2 * lane],     0.f);
    float h1 = fmaxf(di * acc1 + di * di * pv.y + bg1s[2 * lane + 1], 0.f);

    float z = 0.f;
#pragma unroll
    for (int k = 0; k < 32; k++) {
        float h0v = __shfl_sync(0xffffffffu, h0, k);
        float h1v = __shfl_sync(0xffffffffu, h1, k);
        z += h0v * Wg2s[(2 * k) * ZDIM + lane] + h1v * Wg2s[(2 * k + 1) * ZDIM + lane];
    }
    __half* t2 = (__half*)g_t2h;
    t2[(long long)v * 32 + lane] = __float2half_rn(z);
}

// -- gather2: z = aggregate(t2h)+bg2; d = relu(z@Wf1+bf1); store d as fp16 frags --
__global__ __launch_bounds__(256) void gather2_kernel(const float* __restrict__ bg2,
                                                      const float* __restrict__ Wf1,
                                                      const float* __restrict__ bf1) {
    __shared__ float Wf1s[ZDIM * HD];
    __shared__ float bg2s[ZDIM];
    __shared__ float bf1s[HD];
    int tid = threadIdx.x;
    for (int i = tid; i < ZDIM * HD; i += 256) Wf1s[i] = Wf1[i];
    if (tid < ZDIM) bg2s[tid] = bg2[tid];
    if (tid < HD)   bf1s[tid] = bf1[tid];
    __syncthreads();

    int v = blockIdx.x * 8 + (tid >> 5);
    if (v >= NN) return;
    int lane = tid & 31;
    int lp = lane & 15;

    float a0a = 0.f, a0b = 0.f, a1a = 0.f, a1b = 0.f;
    int beg = g_off[v];
    int cnt = g_deg[v];
    for (int base = 0; base < cnt; base += 32) {
        int j = base + lane;
        int s = (j < cnt) ? g_csr[beg + j] : 0;
        float w = (j < cnt) ? g_dinv[s] : 0.f;
        int soff = s * 16;
        int rem = cnt - base;
        if (rem > 32) rem = 32;
        for (int qq = 0; qq * 8 < rem; qq++) {
            unsigned fv[8];
            float wv[8];
#pragma unroll
            for (int qi = 0; qi < 8; qi++) {
                int q = qq * 8 + qi;
                int ov = __shfl_sync(0xffffffffu, soff, q);
                wv[qi] = __shfl_sync(0xffffffffu, w, q);
                fv[qi] = g_t2h[ov + lp];
            }
#pragma unroll
            for (int qi = 0; qi < 8; qi++) {
                float2 f = h2unpack(fv[qi]);
                if (qi & 1) { a0b += wv[qi] * f.x; a1b += wv[qi] * f.y; }
                else        { a0a += wv[qi] * f.x; a1a += wv[qi] * f.y; }
            }
        }
    }
    float acc0 = a0a + a0b, acc1 = a1a + a1b;
    float di = g_dinv[v];
    float2 pv = h2unpack(g_t2h[(long long)v * 16 + lp]);
    float z0 = di * acc0 + di * di * pv.x + bg2s[2 * lp];
    float z1 = di * acc1 + di * di * pv.y + bg2s[2 * lp + 1];

    float e0 = 0.f, e1 = 0.f;
#pragma unroll
    for (int k = 0; k < 16; k++) {
        float z0v = __shfl_sync(0xffffffffu, z0, k);
        float z1v = __shfl_sync(0xffffffffu, z1, k);
        e0 += z0v * Wf1s[(2 * k) * HD + lane]      + z1v * Wf1s[(2 * k + 1) * HD + lane];
        e1 += z0v * Wf1s[(2 * k) * HD + lane + 32] + z1v * Wf1s[(2 * k + 1) * HD + lane + 32];
    }
    float d0 = fmaxf(e0 + bf1s[lane],      0.f);
    float d1 = fmaxf(e1 + bf1s[lane + 32], 0.f);

    __half* dz = (__half*)g_dzp;
    long long b = (long long)v * HD;
    dz[b + lane]      = __float2half_rn(d0);
    dz[b + lane + 32] = __float2half_rn(d1);
}

// ---- decode2 (fp16 tensor core): out = relu(d[N,64] @ Wf2[64,1024] + bf2) ----
__global__ __launch_bounds__(256, 3) void decode2_mma_kernel(const float* __restrict__ bf2,
                                                             float* __restrict__ out) {
    int tid = threadIdx.x;
    int wid = tid >> 5, lane = tid & 31;
    int gid = lane >> 2, tid4 = lane & 3;
    int warpM = wid & 3, warpN = wid >> 2;
    long long rowBase = (long long)blockIdx.x * 64 + warpM * 16;
    int colBase = blockIdx.y * 128 + warpN * 64;

    long long r0 = rowBase + gid;
    long long r1 = r0 + 8;
    long long c0 = (r0 < NN) ? r0 : NN - 1;
    long long c1 = (r1 < NN) ? r1 : NN - 1;
    long long rp0 = c0 * 32, rp1 = c1 * 32;

    float acc[8][4];
#pragma unroll
    for (int nb = 0; nb < 8; nb++)
#pragma unroll
        for (int q = 0; q < 4; q++) acc[nb][q] = 0.f;

#pragma unroll
    for (int kc = 0; kc < 4; kc++) {
        unsigned a[4];
        a[0] = g_dzp[rp0 + kc * 8 + tid4];
        a[1] = g_dzp[rp1 + kc * 8 + tid4];
        a[2] = g_dzp[rp0 + kc * 8 + tid4 + 4];
        a[3] = g_dzp[rp1 + kc * 8 + tid4 + 4];
#pragma unroll
        for (int nb = 0; nb < 8; nb++) {
            int nbg = colBase / 8 + nb;
            uint2 b = *(const uint2*)(g_Wf2p + (kc * 128 + nbg) * 64 + lane * 2);
            mma16816h(acc[nb], a, b.x, b.y);
        }
    }

#pragma unroll
    for (int nb = 0; nb < 8; nb++) {
        int c = colBase + nb * 8 + tid4 * 2;
        float2 bv = *(const float2*)(bf2 + c);
        if (r0 < NN) {
            float2 o = make_float2(fmaxf(acc[nb][0] + bv.x, 0.f),
                                   fmaxf(acc[nb][1] + bv.y, 0.f));
            *(float2*)(out + r0 * CIN + c) = o;
        }
        if (r1 < NN) {
            float2 o = make_float2(fmaxf(acc[nb][2] + bv.x, 0.f),
                                   fmaxf(acc[nb][3] + bv.y, 0.f));
            *(float2*)(out + r1 * CIN + c) = o;
        }
    }
}

// ---------------------------------------------------------------------------
extern "C" void kernel_launch(void* const* d_in, const int* in_sizes, int n_in,
                              void* d_out, int out_size) {
    const float* x    = (const float*)d_in[0];
    const void*  ei   = d_in[1];
    const float* Wg1  = (const float*)d_in[2];
    const float* bg1  = (const float*)d_in[3];
    const float* Wg2  = (const float*)d_in[4];
    const float* bg2  = (const float*)d_in[5];
    const float* Wf1  = (const float*)d_in[6];
    const float* bf1  = (const float*)d_in[7];
    const float* Wf2  = (const float*)d_in[8];
    const float* bf2  = (const float*)d_in[9];
    float* out = (float*)d_out;

    unsigned* wg1p; cudaGetSymbolAddress((void**)&wg1p, g_Wg1p);
    unsigned* wf2p; cudaGetSymbolAddress((void**)&wf2p, g_Wf2p);

    // Launch order puts scatter at profiled index 3 (gemm1 is at its DRAM floor).
    init_kernel<<<NBLK, 256>>>((const int*)ei);                     // 0
    hist_kernel<<<EE / 256, 256>>>(ei);                             // 1
    alloc_kernel<<<NBLK, 256>>>();                                  // 2
    scatter_kernel<<<EE / 256, 256>>>(ei);                          // 3 <- profiled

    pack_w16_kernel<<<128, 256>>>(Wg1, CIN, HD, wg1p);
    gemm1_mma_kernel<<<(NN + 127) / 128, 256>>>(x);
    pack_w16_kernel<<<128, 256>>>(Wf2, HD, CIN, wf2p);

    gather1_kernel<<<(NN + 7) / 8, 256>>>(bg1, Wg2);
    gather2_kernel<<<(NN + 7) / 8, 256>>>(bg2, Wf1, bf1);

    dim3 g2((NN + 63) / 64, CIN / 128);
    decode2_mma_kernel<<<g2, 256>>>(bf2, out);
}

// round 11
// speedup vs baseline: 1.0606x; 1.0606x over previous
#include <cuda_runtime.h>
#include <cuda_fp16.h>

#define NN   100000
#define EE   1600000
#define CIN  1024
#define HD   64
#define ZDIM 32

#define NBLK ((NN + 255) / 256)   // 391

// ---------------- scratch (static __device__ — no allocation) ----------------
__device__ int   g_is64;
__device__ int   g_total;
__device__ int   g_deg[NN];
__device__ int   g_off[NN];
__device__ int   g_cur[NN];
__device__ int   g_csr[EE];
__device__ float g_dinv[NN];
__device__ unsigned g_t1h[NN * 32 + 32];  // dinv-scaled x@Wg1, fp16 half2 (+zero pad row)
__device__ unsigned g_t2h[NN * 16 + 16];  // dinv-scaled encoder z, fp16 half2 (+zero pad row)
__device__ unsigned g_dzp[NN * 32];       // decoder hidden, fp16 half2 frag words

// fp16 frag-packed weights
__device__ __align__(16) unsigned g_Wg1p[64 * 8 * 64];     // 128 KB
__device__ __align__(16) unsigned g_Wf2p[4 * 128 * 64];    // 128 KB

// ---------------- helpers ----------------
__device__ __forceinline__ unsigned h2pack(float x0, float x1) {
    __half2 h = __float22half2_rn(make_float2(x0, x1));
    return *reinterpret_cast<unsigned*>(&h);
}
__device__ __forceinline__ float2 h2unpack(unsigned w) {
    return __half22float2(*reinterpret_cast<__half2*>(&w));
}

__device__ __forceinline__ void mma16816h(float* c, const unsigned* a, unsigned b0, unsigned b1) {
    asm volatile(
        "mma.sync.aligned.m16n8k16.row.col.f32.f16.f16.f32 "
        "{%0,%1,%2,%3}, {%4,%5,%6,%7}, {%8,%9}, {%0,%1,%2,%3};\n"
        : "+f"(c[0]), "+f"(c[1]), "+f"(c[2]), "+f"(c[3])
        : "r"(a[0]), "r"(a[1]), "r"(a[2]), "r"(a[3]), "r"(b0), "r"(b1));
}

__device__ __forceinline__ void cp16(unsigned smem_addr, const void* gptr) {
    asm volatile("cp.async.ca.shared.global [%0], [%1], 16;\n"
                 :: "r"(smem_addr), "l"(gptr));
}
__device__ __forceinline__ void cp_commit() { asm volatile("cp.async.commit_group;\n"); }
__device__ __forceinline__ void cp_wait1()  { asm volatile("cp.async.wait_group 1;\n" ::: "memory"); }

// ---------------- weight pack helper (device) ----------------
__device__ __forceinline__ void pack_one(const float* __restrict__ W, int K, int N,
                                         unsigned* __restrict__ pw, int idx) {
    int lane2 = idx & 63;
    int j = lane2 & 1;
    int lane = lane2 >> 1;
    int nb = (idx >> 6) % (N / 8);
    int kc = idx / (64 * (N / 8));
    int k0 = kc * 16 + (lane & 3) * 2 + j * 8;
    int n = nb * 8 + (lane >> 2);
    pw[idx] = h2pack(W[(long long)k0 * N + n], W[(long long)(k0 + 1) * N + n]);
}

// ---------------- prep: detect dtype, zero deg, zero pads, pack both weights ----------------
__global__ void prep_kernel(const int* __restrict__ ei32,
                            const float* __restrict__ Wg1,
                            const float* __restrict__ Wf2) {
    int i = blockIdx.x * blockDim.x + threadIdx.x;
    if (i < NN) g_deg[i] = 0;
    if (i < 32) g_t1h[NN * 32 + i] = 0;
    if (i < 16) g_t2h[NN * 16 + i] = 0;
    if (i == 0) {
        int nz = 0;
        for (int k = 0; k < 64; k++) nz |= (ei32[2 * k + 1] != 0);
        g_is64 = nz ? 0 : 1;
        g_total = 0;
    }
    if (i < 64 * 8 * 64) {
        pack_one(Wg1, CIN, HD, g_Wg1p, i);
        pack_one(Wf2, HD, CIN, g_Wf2p, i);
    }
}

__global__ void hist_kernel(const void* __restrict__ ei) {
    int is64 = g_is64;
    int e = blockIdx.x * blockDim.x + threadIdx.x;
    if (e < EE) {
        int d = is64 ? (int)((const long long*)ei)[EE + e]
                     : ((const int*)ei)[EE + e];
        atomicAdd(&g_deg[d], 1);
    }
}

// ---- alloc: warp-aggregated offset assignment ----
__global__ void alloc_kernel() {
    int i = blockIdx.x * blockDim.x + threadIdx.x;
    int lane = threadIdx.x & 31;
    int d = (i < NN) ? g_deg[i] : 0;
    int p = d;
#pragma unroll
    for (int o = 1; o < 32; o <<= 1) {
        int t = __shfl_up_sync(0xffffffffu, p, o);
        if (lane >= o) p += t;
    }
    int tot = __shfl_sync(0xffffffffu, p, 31);
    int base = 0;
    if (lane == 31) base = atomicAdd(&g_total, tot);
    base = __shfl_sync(0xffffffffu, base, 31);
    if (i < NN) {
        int off = base + p - d;
        g_off[i] = off;
        g_cur[i] = off;
        g_dinv[i] = rsqrtf((float)(d + 1));
    }
}

__global__ void scatter_kernel(const void* __restrict__ ei) {
    int is64 = g_is64;
    int e = blockIdx.x * blockDim.x + threadIdx.x;
    if (e < EE) {
        int s, d;
        if (is64) {
            s = (int)((const long long*)ei)[e];
            d = (int)((const long long*)ei)[EE + e];
        } else {
            s = ((const int*)ei)[e];
            d = ((const int*)ei)[EE + e];
        }
        int pos = atomicAdd(&g_cur[d], 1);
        g_csr[pos] = s;
    }
}

// -------- GEMM1 (fp16 tensor core): t1h[N,64] = dinv .* (x[N,1024] @ Wg1) --------
__global__ __launch_bounds__(256, 3) void gemm1_mma_kernel(const float* __restrict__ x) {
    __shared__ __align__(16) unsigned Bs[3 * 512];
    int tid = threadIdx.x;
    int wid = tid >> 5, lane = tid & 31;
    int gid = lane >> 2, tid4 = lane & 3;
    long long rowBase = (long long)blockIdx.x * 128 + wid * 16;

    long long r0 = rowBase + gid;
    long long r1 = r0 + 8;
    long long c0 = (r0 < NN) ? r0 : NN - 1;
    long long c1 = (r1 < NN) ? r1 : NN - 1;
    const float* p0 = x + c0 * CIN;
    const float* p1 = x + c1 * CIN;

    unsigned sbase = (unsigned)__cvta_generic_to_shared(Bs);
    int doCp = (tid < 128);

    if (doCp) cp16(sbase + tid * 16, g_Wg1p + tid * 4);
    cp_commit();
    if (doCp) cp16(sbase + 512 * 4 + tid * 16, g_Wg1p + 512 + tid * 4);
    cp_commit();

    float acc[8][4];
#pragma unroll
    for (int nb = 0; nb < 8; nb++)
#pragma unroll
        for (int q = 0; q < 4; q++) acc[nb][q] = 0.f;

    float2 a0, a1, a2, a3;
    {
        int col = tid4 * 2;
        a0 = *(const float2*)(p0 + col);
        a1 = *(const float2*)(p1 + col);
        a2 = *(const float2*)(p0 + col + 8);
        a3 = *(const float2*)(p1 + col + 8);
    }

    for (int kc = 0; kc < 64; kc++) {
        float2 n0, n1, n2, n3;
        if (kc < 63) {
            int col = (kc + 1) * 16 + tid4 * 2;
            n0 = *(const float2*)(p0 + col);
            n1 = *(const float2*)(p1 + col);
            n2 = *(const float2*)(p0 + col + 8);
            n3 = *(const float2*)(p1 + col + 8);
        }

        cp_wait1();
        __syncthreads();
        if (kc + 2 < 64 && doCp)
            cp16(sbase + ((kc + 2) % 3) * 512 * 4 + tid * 16, g_Wg1p + (kc + 2) * 512 + tid * 4);
        cp_commit();

        unsigned at[4];
        at[0] = h2pack(a0.x, a0.y);
        at[1] = h2pack(a1.x, a1.y);
        at[2] = h2pack(a2.x, a2.y);
        at[3] = h2pack(a3.x, a3.y);

        const unsigned* BsS = Bs + (kc % 3) * 512;
#pragma unroll
        for (int nb = 0; nb < 8; nb++) {
            uint2 b = *(const uint2*)(BsS + nb * 64 + lane * 2);
            mma16816h(acc[nb], at, b.x, b.y);
        }
        a0 = n0; a1 = n1; a2 = n2; a3 = n3;
    }

    // epilogue: scale by dinv[row], pack adjacent column pairs
    float di0 = (r0 < NN) ? g_dinv[r0] : 0.f;
    float di1 = (r1 < NN) ? g_dinv[r1] : 0.f;
#pragma unroll
    for (int nb = 0; nb < 8; nb++) {
        int w = nb * 4 + tid4;
        if (r0 < NN) g_t1h[r0 * 32 + w] = h2pack(acc[nb][0] * di0, acc[nb][1] * di0);
        if (r1 < NN) g_t1h[r1 * 32 + w] = h2pack(acc[nb][2] * di1, acc[nb][3] * di1);
    }
}

// ------- gather1: plain-sum aggregate(t1h); h = relu(di*. + bg1); t2h = dinv.*(h@Wg2) -------
__global__ __launch_bounds__(256) void gather1_kernel(const float* __restrict__ bg1,
                                                      const float* __restrict__ Wg2) {
    __shared__ float Wg2s[HD * ZDIM];
    __shared__ float bg1s[HD];
    int tid = threadIdx.x;
    for (int i = tid; i < HD * ZDIM; i += 256) Wg2s[i] = Wg2[i];
    if (tid < HD) bg1s[tid] = bg1[tid];
    __syncthreads();

    int v = blockIdx.x * 8 + (tid >> 5);
    if (v >= NN) return;
    int lane = tid & 31;

    float a0a = 0.f, a0b = 0.f, a1a = 0.f, a1b = 0.f;
    int beg = g_off[v];
    int cnt = g_deg[v];
    for (int base = 0; base < cnt; base += 32) {
        int j = base + lane;
        int soff = (j < cnt) ? g_csr[beg + j] * 32 : NN * 32;
        int rem = cnt - base;
        if (rem > 32) rem = 32;
#pragma unroll
        for (int qq = 0; qq < 4; qq++) {
            if (qq * 8 >= rem) break;
#pragma unroll
            for (int qi = 0; qi < 8; qi++) {
                int ov = __shfl_sync(0xffffffffu, soff, qq * 8 + qi);
                float2 f = h2unpack(g_t1h[ov + lane]);
                if (qi & 1) { a0b += f.x; a1b += f.y; }
                else        { a0a += f.x; a1a += f.y; }
            }
        }
    }
    float di = g_dinv[v];
    float2 pv = h2unpack(g_t1h[(long long)v * 32 + lane]);   // already dinv_v-scaled
    float h0 = fmaxf(di * (a0a + a0b + pv.x) + bg1s[2 * lane],     0.f);
    float h1 = fmaxf(di * (a1a + a1b + pv.y) + bg1s[2 * lane + 1], 0.f);

    // z[n] = sum_k h[k] * Wg2[k][n]; store dinv_v * z
    float z = 0.f;
#pragma unroll
    for (int k = 0; k < 32; k++) {
        float h0v = __shfl_sync(0xffffffffu, h0, k);
        float h1v = __shfl_sync(0xffffffffu, h1, k);
        z += h0v * Wg2s[(2 * k) * ZDIM + lane] + h1v * Wg2s[(2 * k + 1) * ZDIM + lane];
    }
    __half* t2 = (__half*)g_t2h;
    t2[(long long)v * 32 + lane] = __float2half_rn(di * z);
}

// -- gather2: z = di*(plain-sum(t2h)+self)+bg2; d = relu(z@Wf1+bf1); store fp16 frags --
__global__ __launch_bounds__(256) void gather2_kernel(const float* __restrict__ bg2,
                                                      const float* __restrict__ Wf1,
                                                      const float* __restrict__ bf1) {
    __shared__ float Wf1s[ZDIM * HD];
    __shared__ float bg2s[ZDIM];
    __shared__ float bf1s[HD];
    int tid = threadIdx.x;
    for (int i = tid; i < ZDIM * HD; i += 256) Wf1s[i] = Wf1[i];
    if (tid < ZDIM) bg2s[tid] = bg2[tid];
    if (tid < HD)   bf1s[tid] = bf1[tid];
    __syncthreads();

    int v = blockIdx.x * 8 + (tid >> 5);
    if (v >= NN) return;
    int lane = tid & 31;
    int lp = lane & 15;

    float a0a = 0.f, a0b = 0.f, a1a = 0.f, a1b = 0.f;
    int beg = g_off[v];
    int cnt = g_deg[v];
    for (int base = 0; base < cnt; base += 32) {
        int j = base + lane;
        int soff = (j < cnt) ? g_csr[beg + j] * 16 : NN * 16;
        int rem = cnt - base;
        if (rem > 32) rem = 32;
#pragma unroll
        for (int qq = 0; qq < 4; qq++) {
            if (qq * 8 >= rem) break;
#pragma unroll
            for (int qi = 0; qi < 8; qi++) {
                int ov = __shfl_sync(0xffffffffu, soff, qq * 8 + qi);
                float2 f = h2unpack(g_t2h[ov + lp]);
                if (qi & 1) { a0b += f.x; a1b += f.y; }
                else        { a0a += f.x; a1a += f.y; }
            }
        }
    }
    float di = g_dinv[v];
    float2 pv = h2unpack(g_t2h[(long long)v * 16 + lp]);   // already dinv_v-scaled
    float z0 = di * (a0a + a0b + pv.x) + bg2s[2 * lp];
    float z1 = di * (a1a + a1b + pv.y) + bg2s[2 * lp + 1];

    float e0 = 0.f, e1 = 0.f;
#pragma unroll
    for (int k = 0; k < 16; k++) {
        float z0v = __shfl_sync(0xffffffffu, z0, k);
        float z1v = __shfl_sync(0xffffffffu, z1, k);
        e0 += z0v * Wf1s[(2 * k) * HD + lane]      + z1v * Wf1s[(2 * k + 1) * HD + lane];
        e1 += z0v * Wf1s[(2 * k) * HD + lane + 32] + z1v * Wf1s[(2 * k + 1) * HD + lane + 32];
    }
    float d0 = fmaxf(e0 + bf1s[lane],      0.f);
    float d1 = fmaxf(e1 + bf1s[lane + 32], 0.f);

    __half* dz = (__half*)g_dzp;
    long long b = (long long)v * HD;
    dz[b + lane]      = __float2half_rn(d0);
    dz[b + lane + 32] = __float2half_rn(d1);
}

// ---- decode2 (fp16 tensor core): out = relu(d[N,64] @ Wf2[64,1024] + bf2) ----
__global__ __launch_bounds__(256, 3) void decode2_mma_kernel(const float* __restrict__ bf2,
                                                             float* __restrict__ out) {
    int tid = threadIdx.x;
    int wid = tid >> 5, lane = tid & 31;
    int gid = lane >> 2, tid4 = lane & 3;
    int warpM = wid & 3, warpN = wid >> 2;
    long long rowBase = (long long)blockIdx.x * 64 + warpM * 16;
    int colBase = blockIdx.y * 128 + warpN * 64;

    long long r0 = rowBase + gid;
    long long r1 = r0 + 8;
    long long c0 = (r0 < NN) ? r0 : NN - 1;
    long long c1 = (r1 < NN) ? r1 : NN - 1;
    long long rp0 = c0 * 32, rp1 = c1 * 32;

    float acc[8][4];
#pragma unroll
    for (int nb = 0; nb < 8; nb++)
#pragma unroll
        for (int q = 0; q < 4; q++) acc[nb][q] = 0.f;

#pragma unroll
    for (int kc = 0; kc < 4; kc++) {
        unsigned a[4];
        a[0] = g_dzp[rp0 + kc * 8 + tid4];
        a[1] = g_dzp[rp1 + kc * 8 + tid4];
        a[2] = g_dzp[rp0 + kc * 8 + tid4 + 4];
        a[3] = g_dzp[rp1 + kc * 8 + tid4 + 4];
#pragma unroll
        for (int nb = 0; nb < 8; nb++) {
            int nbg = colBase / 8 + nb;
            uint2 b = *(const uint2*)(g_Wf2p + (kc * 128 + nbg) * 64 + lane * 2);
            mma16816h(acc[nb], a, b.x, b.y);
        }
    }

#pragma unroll
    for (int nb = 0; nb < 8; nb++) {
        int c = colBase + nb * 8 + tid4 * 2;
        float2 bv = *(const float2*)(bf2 + c);
        if (r0 < NN) {
            float2 o = make_float2(fmaxf(acc[nb][0] + bv.x, 0.f),
                                   fmaxf(acc[nb][1] + bv.y, 0.f));
            *(float2*)(out + r0 * CIN + c) = o;
        }
        if (r1 < NN) {
            float2 o = make_float2(fmaxf(acc[nb][2] + bv.x, 0.f),
                                   fmaxf(acc[nb][3] + bv.y, 0.f));
            *(float2*)(out + r1 * CIN + c) = o;
        }
    }
}

// ---------------------------------------------------------------------------
extern "C" void kernel_launch(void* const* d_in, const int* in_sizes, int n_in,
                              void* d_out, int out_size) {
    const float* x    = (const float*)d_in[0];
    const void*  ei   = d_in[1];
    const float* Wg1  = (const float*)d_in[2];
    const float* bg1  = (const float*)d_in[3];
    const float* Wg2  = (const float*)d_in[4];
    const float* bg2  = (const float*)d_in[5];
    const float* Wf1  = (const float*)d_in[6];
    const float* bf1  = (const float*)d_in[7];
    const float* Wf2  = (const float*)d_in[8];
    const float* bf2  = (const float*)d_in[9];
    float* out = (float*)d_out;

    // gemm1 at profiled slot 4; needs dinv (alloc) and packed Wg1 (prep).
    prep_kernel<<<NBLK, 256>>>((const int*)ei, Wg1, Wf2);           // 1
    hist_kernel<<<EE / 256, 256>>>(ei);                             // 2
    alloc_kernel<<<NBLK, 256>>>();                                  // 3
    gemm1_mma_kernel<<<(NN + 127) / 128, 256>>>(x);                 // 4 <- profiled

    scatter_kernel<<<EE / 256, 256>>>(ei);                          // 5
    gather1_kernel<<<(NN + 7) / 8, 256>>>(bg1, Wg2);                // 6
    gather2_kernel<<<(NN + 7) / 8, 256>>>(bg2, Wf1, bf1);           // 7

    dim3 g2((NN + 63) / 64, CIN / 128);
    decode2_mma_kernel<<<g2, 256>>>(bf2, out);                      // 8
}